// round 5
// baseline (speedup 1.0000x reference)
#include <cuda_runtime.h>
#include <math.h>

#define NB 32768
#define NN 1024
#define NM 64
#define KTOT 128
#define TM 32
#define THREADS 256
#define NSTAGE 16
#define WSTAGE_F2 4096    // 16 ks * 4 chunks * 64 pairs per stage

// ---- device-global scratch (no allocations allowed) ----
__device__ __align__(16) float  g_logprior[NN];
__device__ __align__(16) float  g_inv_sd[NM];
__device__ __align__(16) float2 g_W[NSTAGE * WSTAGE_F2];   // 512 KB

typedef unsigned long long ull;

__device__ __forceinline__ void fma2(ull& d, ull a, ull b) {
    asm("fma.rn.f32x2 %0, %1, %2, %0;" : "+l"(d) : "l"(a), "l"(b));
}
__device__ __forceinline__ float2 asf2(ull v) {
    float2 r; asm("mov.b64 {%0,%1}, %2;" : "=f"(r.x), "=f"(r.y) : "l"(v)); return r;
}
__device__ __forceinline__ unsigned su32(const void* p) {
    return (unsigned)__cvta_generic_to_shared(p);
}
__device__ __forceinline__ void cp16(unsigned s, const void* g) {
    asm volatile("cp.async.cg.shared.global [%0], [%1], 16;" :: "r"(s), "l"(g) : "memory");
}

// ---- single prep kernel: block 0 builds inv_sd + log_softmax(lm); all blocks build W ----
__global__ void prep_all(const float* __restrict__ C, const float* __restrict__ sd,
                         const float* __restrict__ lm) {
    __shared__ float red[THREADS];
    int t = threadIdx.x;
    if (blockIdx.x == 0) {
        if (t < NM) g_inv_sd[t] = 1.0f / sd[t];
        float mx = -1e30f;
        for (int i = t; i < NN; i += THREADS) mx = fmaxf(mx, lm[i]);
        red[t] = mx; __syncthreads();
        for (int s = THREADS / 2; s > 0; s >>= 1) {
            if (t < s) red[t] = fmaxf(red[t], red[t + s]);
            __syncthreads();
        }
        mx = red[0]; __syncthreads();
        float sum = 0.f;
        for (int i = t; i < NN; i += THREADS) sum += expf(lm[i] - mx);
        red[t] = sum; __syncthreads();
        for (int s = THREADS / 2; s > 0; s >>= 1) {
            if (t < s) red[t] += red[t + s];
            __syncthreads();
        }
        float lse = mx + logf(red[0]);
        for (int i = t; i < NN; i += THREADS) g_logprior[i] = lm[i] - lse;
    }
    // W layout: [stage16][kp16][chunk4][pair64] as float2 over cols (pair*2, pair*2+1)
    int idx = blockIdx.x * blockDim.x + t;
    if (idx >= NSTAGE * WSTAGE_F2) return;
    int pair = idx & 63;
    int ch   = (idx >> 6) & 3;
    int kp   = (idx >> 8) & 15;
    int sg   = idx >> 12;          // global stage 0..15
    int pass = sg >> 3;            // col pass 0/1
    int st   = sg & 7;             // k-stage within pass
    int k    = st * 16 + kp;       // folded k 0..127
    int gc   = pass * 4 + ch;      // global chunk 0..7
    int n0   = gc * 128 + pair * 2;
    float2 v;
    if (k < NM) {
        v.x = C[(size_t)n0 * NM + k];
        v.y = C[(size_t)(n0 + 1) * NM + k];
    } else {
        float c0 = C[(size_t)n0 * NM + k - NM];
        float c1 = C[(size_t)(n0 + 1) * NM + k - NM];
        v.x = -0.5f * c0 * c0;
        v.y = -0.5f * c1 * c1;
    }
    g_W[idx] = v;
}

// ---- main fused kernel ----
#define SMEM_LOGITS 0
#define SMEM_UD     (TM * NN * 4)                  // 131072
#define SMEM_W      (SMEM_UD + TM * KTOT * 8)      // 163840
#define SMEM_CB     (SMEM_W + 2 * WSTAGE_F2 * 8)   // 229376
#define SMEM_TOTAL  (SMEM_CB + TM * 4)             // 229504

__global__ __launch_bounds__(THREADS, 1)
void rmm_main(const float* __restrict__ samples, const float* __restrict__ mask,
              float* __restrict__ out) {
    extern __shared__ char smem[];
    float*  sLog = (float*)(smem + SMEM_LOGITS);
    float2* sUd  = (float2*)(smem + SMEM_UD);
    float2* sW   = (float2*)(smem + SMEM_W);
    float*  sCb  = (float*)(smem + SMEM_CB);

    const int t    = threadIdx.x;
    const int warp = t >> 5;
    const int lane = t & 31;
    const int r0   = blockIdx.x * TM;

    // prologue: kick off stage-0 W panel copy (32 KB)
    {
        const float4* src = (const float4*)(g_W);
        float4* dstb = (float4*)sW;
        #pragma unroll
        for (int i = 0; i < 8; i++)
            cp16(su32(dstb + t + i * THREADS), src + t + i * THREADS);
        asm volatile("cp.async.commit_group;" ::: "memory");
    }

    // phase 0: build duplicated U rows and cb
    {
        int prow = t >> 3;
        int j0   = (t & 7) * 8;
        const float4* s4 = (const float4*)(samples + (size_t)(r0 + prow) * NM + j0);
        const float4* m4 = (const float4*)(mask    + (size_t)(r0 + prow) * NM + j0);
        float cbp = 0.f;
        #pragma unroll
        for (int q = 0; q < 2; q++) {
            float4 sv = s4[q];
            float4 mv = m4[q];
            int j = j0 + q * 4;
            float4 iv = *(const float4*)(g_inv_sd + j);
            float mm, sq, u;
            mm = mv.x * iv.x; sq = mm * mm; u = sq * sv.x; cbp += u * sv.x;
            sUd[prow * KTOT + j + 0] = make_float2(u, u);
            sUd[prow * KTOT + NM + j + 0] = make_float2(sq, sq);
            mm = mv.y * iv.y; sq = mm * mm; u = sq * sv.y; cbp += u * sv.y;
            sUd[prow * KTOT + j + 1] = make_float2(u, u);
            sUd[prow * KTOT + NM + j + 1] = make_float2(sq, sq);
            mm = mv.z * iv.z; sq = mm * mm; u = sq * sv.z; cbp += u * sv.z;
            sUd[prow * KTOT + j + 2] = make_float2(u, u);
            sUd[prow * KTOT + NM + j + 2] = make_float2(sq, sq);
            mm = mv.w * iv.w; sq = mm * mm; u = sq * sv.w; cbp += u * sv.w;
            sUd[prow * KTOT + j + 3] = make_float2(u, u);
            sUd[prow * KTOT + NM + j + 3] = make_float2(sq, sq);
        }
        cbp += __shfl_xor_sync(0xffffffffu, cbp, 1);
        cbp += __shfl_xor_sync(0xffffffffu, cbp, 2);
        cbp += __shfl_xor_sync(0xffffffffu, cbp, 4);
        if ((t & 7) == 0) sCb[prow] = -0.5f * cbp;
    }

    // mapping: warp -> (chunk = warp>>1, row half = warp&1); lane -> pairs lane & lane+32
    const int mych  = warp >> 1;           // chunk within the 4-chunk pass
    const int rbase = (warp & 1) * 16;     // 16 rows per warp
    const ulonglong2* uBase = (const ulonglong2*)(sUd) + rbase * 64;  // 64 ull2 per row

    ull acc0[16], acc1[16];
    #pragma unroll
    for (int i = 0; i < 16; i++) { acc0[i] = 0ull; acc1[i] = 0ull; }

    __syncthreads();

    #pragma unroll 1
    for (int s = 0; s < NSTAGE; s++) {
        asm volatile("cp.async.wait_group 0;" ::: "memory");
        __syncthreads();
        if (s + 1 < NSTAGE) {
            const float4* src = (const float4*)(g_W + (size_t)(s + 1) * WSTAGE_F2);
            float4* dstb = (float4*)(sW + ((s + 1) & 1) * WSTAGE_F2);
            #pragma unroll
            for (int i = 0; i < 8; i++)
                cp16(su32(dstb + t + i * THREADS), src + t + i * THREADS);
            asm volatile("cp.async.commit_group;" ::: "memory");
        }

        const ull* wbL = (const ull*)(sW + (s & 1) * WSTAGE_F2) + mych * 64 + lane;
        const ulonglong2* uS = uBase + (s & 7) * 8;

        #pragma unroll
        for (int kk = 0; kk < 8; kk++) {
            ull b00 = wbL[(2 * kk) * 256];
            ull b01 = wbL[(2 * kk + 1) * 256];
            ull b10 = wbL[(2 * kk) * 256 + 32];
            ull b11 = wbL[(2 * kk + 1) * 256 + 32];
            #pragma unroll
            for (int r = 0; r < 16; r++) {
                ulonglong2 a = uS[r * 64 + kk];
                fma2(acc0[r], a.x, b00); fma2(acc0[r], a.y, b01);
                fma2(acc1[r], a.x, b10); fma2(acc1[r], a.y, b11);
            }
        }

        if ((s & 7) == 7) {   // pass complete for this warp's chunk -> logits
            int gc = (s >> 3) * 4 + mych;
            int c0 = gc * 128 + lane * 2;
            float2 lp0 = *(const float2*)(g_logprior + c0);
            float2 lp1 = *(const float2*)(g_logprior + c0 + 64);
            #pragma unroll
            for (int r = 0; r < 16; r++) {
                float cb = sCb[rbase + r];
                float2 a0 = asf2(acc0[r]);
                float2 a1 = asf2(acc1[r]);
                float2 v0 = make_float2(lp0.x + fminf(a0.x + cb, 0.f),
                                        lp0.y + fminf(a0.y + cb, 0.f));
                float2 v1 = make_float2(lp1.x + fminf(a1.x + cb, 0.f),
                                        lp1.y + fminf(a1.y + cb, 0.f));
                float* row = sLog + (size_t)(rbase + r) * NN + c0;
                *(float2*)(row)      = v0;
                *(float2*)(row + 64) = v1;
                acc0[r] = 0ull; acc1[r] = 0ull;
            }
        }
    }
    __syncthreads();

    // phase 2: per-row truncated softmax (first softmax's normalizer cancels)
    float* pdf_out  = out;
    float* lpdf_out = out + (size_t)NB * NN;
    #pragma unroll 1
    for (int rr = 0; rr < 4; rr++) {
        int row = rr * 8 + warp;
        const float4* L4 = (const float4*)(sLog + (size_t)row * NN);
        float4 x[8];
        #pragma unroll
        for (int i = 0; i < 8; i++) x[i] = L4[lane + 32 * i];
        float mx = -1e30f;
        #pragma unroll
        for (int i = 0; i < 8; i++)
            mx = fmaxf(mx, fmaxf(fmaxf(x[i].x, x[i].y), fmaxf(x[i].z, x[i].w)));
        #pragma unroll
        for (int o = 16; o > 0; o >>= 1)
            mx = fmaxf(mx, __shfl_xor_sync(0xffffffffu, mx, o));
        float ssum = 0.f;
        #pragma unroll
        for (int i = 0; i < 8; i++) {
            float4 v = x[i];
            float p0 = __expf(v.x - mx); p0 = (p0 > 0.05f) ? p0 : 0.f;
            float p1 = __expf(v.y - mx); p1 = (p1 > 0.05f) ? p1 : 0.f;
            float p2 = __expf(v.z - mx); p2 = (p2 > 0.05f) ? p2 : 0.f;
            float p3 = __expf(v.w - mx); p3 = (p3 > 0.05f) ? p3 : 0.f;
            x[i] = make_float4(p0, p1, p2, p3);
            ssum += (p0 + p1) + (p2 + p3);
        }
        #pragma unroll
        for (int o = 16; o > 0; o >>= 1)
            ssum += __shfl_xor_sync(0xffffffffu, ssum, o);
        float inv = 1.0f / ssum;
        size_t rb = (size_t)(r0 + row) * NN;
        float4* po = (float4*)(pdf_out + rb);
        float4* lo = (float4*)(lpdf_out + rb);
        #pragma unroll
        for (int i = 0; i < 8; i++) {
            float4 v = x[i];
            float4 P = make_float4(v.x * inv, v.y * inv, v.z * inv, v.w * inv);
            float4 L = make_float4(__logf(P.x + 1e-20f), __logf(P.y + 1e-20f),
                                   __logf(P.z + 1e-20f), __logf(P.w + 1e-20f));
            po[lane + 32 * i] = P;
            lo[lane + 32 * i] = L;
        }
    }
}

extern "C" void kernel_launch(void* const* d_in, const int* in_sizes, int n_in,
                              void* d_out, int out_size) {
    const float* samples = (const float*)d_in[0];
    const float* mask    = (const float*)d_in[1];
    const float* cent    = (const float*)d_in[2];
    const float* sd      = (const float*)d_in[3];
    const float* lm      = (const float*)d_in[4];
    float* out = (float*)d_out;
    (void)in_sizes; (void)n_in; (void)out_size;

    cudaFuncSetAttribute(rmm_main, cudaFuncAttributeMaxDynamicSharedMemorySize, SMEM_TOTAL);

    prep_all<<<(NSTAGE * WSTAGE_F2 + THREADS - 1) / THREADS, THREADS>>>(cent, sd, lm);
    rmm_main<<<NB / TM, THREADS, SMEM_TOTAL>>>(samples, mask, out);
}

// round 8
// speedup vs baseline: 1.1685x; 1.1685x over previous
#include <cuda_runtime.h>
#include <cuda_bf16.h>
#include <math.h>
#include <stdint.h>

#define NB 32768
#define NN 1024
#define NM 64

// smem map (kernel1)
#define SM_A   0                 // 3 levels x 32768
#define SM_B   98304             // 2 x 65536
#define SM_CB  229376            // 128 floats
#define SM_RM  229888            // 4 x 128 floats
#define SM_TOT 231936

__device__ __align__(16) unsigned char g_Wb[24 * 65536];  // 1.5 MB frag-linear B
__device__ __align__(16) float g_logprior[NN];
__device__ __align__(16) float g_inv_sd[NM];
__device__ float g_rowmax[NB];

__device__ __forceinline__ uint32_t smem_u32(const void* p) {
    return (uint32_t)__cvta_generic_to_shared(p);
}
__device__ __forceinline__ void cp16(uint32_t s, const void* g) {
    asm volatile("cp.async.cg.shared.global [%0], [%1], 16;" :: "r"(s), "l"(g) : "memory");
}
__device__ __forceinline__ uint4 lds128(uint32_t a) {
    uint4 v;
    asm volatile("ld.shared.v4.b32 {%0,%1,%2,%3}, [%4];"
                 : "=r"(v.x), "=r"(v.y), "=r"(v.z), "=r"(v.w) : "r"(a));
    return v;
}
__device__ __forceinline__ uint2 lds64(uint32_t a) {
    uint2 v;
    asm volatile("ld.shared.v2.b32 {%0,%1}, [%2];" : "=r"(v.x), "=r"(v.y) : "r"(a));
    return v;
}
__device__ __forceinline__ void sts128(uint32_t a, uint32_t x, uint32_t y, uint32_t z, uint32_t w) {
    asm volatile("st.shared.v4.b32 [%0], {%1,%2,%3,%4};" :: "r"(a), "r"(x), "r"(y), "r"(z), "r"(w) : "memory");
}
__device__ __forceinline__ void mma16816(float* c, uint4 a, uint2 b) {
    asm volatile("mma.sync.aligned.m16n8k16.row.col.f32.bf16.bf16.f32 "
                 "{%0,%1,%2,%3}, {%4,%5,%6,%7}, {%8,%9}, {%0,%1,%2,%3};"
                 : "+f"(c[0]), "+f"(c[1]), "+f"(c[2]), "+f"(c[3])
                 : "r"(a.x), "r"(a.y), "r"(a.z), "r"(a.w), "r"(b.x), "r"(b.y));
}
__device__ __forceinline__ void split3(float2 v, uint32_t& u0, uint32_t& u1, uint32_t& u2) {
    __nv_bfloat162 h0 = __floats2bfloat162_rn(v.x, v.y);
    float rx = v.x - __bfloat162float(__low2bfloat16(h0));
    float ry = v.y - __bfloat162float(__high2bfloat16(h0));
    __nv_bfloat162 h1 = __floats2bfloat162_rn(rx, ry);
    rx -= __bfloat162float(__low2bfloat16(h1));
    ry -= __bfloat162float(__high2bfloat16(h1));
    __nv_bfloat162 h2 = __floats2bfloat162_rn(rx, ry);
    u0 = *(uint32_t*)&h0; u1 = *(uint32_t*)&h1; u2 = *(uint32_t*)&h2;
}
__device__ __forceinline__ unsigned short bflvl(float w, int lvl) {
    __nv_bfloat16 b0 = __float2bfloat16(w);
    if (lvl == 0) return *(unsigned short*)&b0;
    float r = w - __bfloat162float(b0);
    __nv_bfloat16 b1 = __float2bfloat16(r);
    if (lvl == 1) return *(unsigned short*)&b1;
    __nv_bfloat16 b2 = __float2bfloat16(r - __bfloat162float(b1));
    return *(unsigned short*)&b2;
}

// ---- prep: logprior + inv_sd + frag-linear bf16 B panels ----
__global__ void prep_all(const float* __restrict__ C, const float* __restrict__ sd,
                         const float* __restrict__ lm) {
    __shared__ float red[256];
    const int t = threadIdx.x;
    if (blockIdx.x == 0) {
        if (t < NM) g_inv_sd[t] = 1.0f / sd[t];
        float mx = -1e30f;
        for (int i = t; i < NN; i += 256) mx = fmaxf(mx, lm[i]);
        red[t] = mx; __syncthreads();
        for (int s = 128; s > 0; s >>= 1) {
            if (t < s) red[t] = fmaxf(red[t], red[t + s]);
            __syncthreads();
        }
        mx = red[0]; __syncthreads();
        float sum = 0.f;
        for (int i = t; i < NN; i += 256) sum += expf(lm[i] - mx);
        red[t] = sum; __syncthreads();
        for (int s = 128; s > 0; s >>= 1) {
            if (t < s) red[t] += red[t + s];
            __syncthreads();
        }
        float lse = mx + logf(red[0]);
        for (int i = t; i < NN; i += 256) g_logprior[i] = lm[i] - lse;
    }
    int idx = blockIdx.x * 256 + t;          // 0..196607, one 8-byte frag pair each
    int lane  = idx & 31;
    int ntile = (idx >> 5) & 31;
    int kstep = (idx >> 10) & 7;
    int u     = idx >> 13;                   // unit 0..23
    int chunk = u / 6, pass = u - chunk * 6;
    const int blv = (pass == 1 || pass == 3) ? 1 : ((pass == 4) ? 2 : 0);
    int col = chunk * 256 + ntile * 8 + (lane >> 2);
    int k0  = kstep * 16 + 2 * (lane & 3);
    float w[4];
    #pragma unroll
    for (int q = 0; q < 4; q++) {
        int k = k0 + (q >> 1) * 8 + (q & 1);
        if (k < NM) w[q] = C[(size_t)col * NM + k];
        else { float c = C[(size_t)col * NM + (k - NM)]; w[q] = -0.5f * c * c; }
    }
    uint32_t r0 = (uint32_t)bflvl(w[0], blv) | ((uint32_t)bflvl(w[1], blv) << 16);
    uint32_t r1 = (uint32_t)bflvl(w[2], blv) | ((uint32_t)bflvl(w[3], blv) << 16);
    ((uint2*)g_Wb)[idx] = make_uint2(r0, r1);
}

// ---- kernel 1: HMMA GEMM + logits + rowmax ----
__global__ __launch_bounds__(256, 1)
void gemm_logits(const float* __restrict__ samples, const float* __restrict__ mask,
                 float* __restrict__ out) {
    extern __shared__ unsigned char smem[];
    const uint32_t sb = smem_u32(smem);
    float* sCb  = (float*)(smem + SM_CB);
    float* sRm  = (float*)(smem + SM_RM);
    float* Ubuf = (float*)(smem + SM_B + 65536);   // aliases B buf1 (pre-loop only)
    const int t = threadIdx.x, warp = t >> 5, lane = t & 31;
    const int r0 = blockIdx.x * 128;
    const int wm = warp & 1, wn = warp >> 1;

    // prefetch unit 0 into B buf0
    {
        const char* src = (const char*)g_Wb + (size_t)t * 16;
        uint32_t dst = sb + SM_B + (uint32_t)t * 16;
        #pragma unroll
        for (int i = 0; i < 16; i++) cp16(dst + i * 4096, src + (size_t)i * 4096);
        asm volatile("cp.async.commit_group;" ::: "memory");
    }

    // step 1: U (folded operand) + cb into smem
    {
        int row = t >> 1, h = t & 1;
        const float4* M4 = (const float4*)(mask    + (size_t)(r0 + row) * NM);
        const float4* S4 = (const float4*)(samples + (size_t)(r0 + row) * NM);
        float4* Ud = (float4*)(Ubuf + row * 128 + h * 64);
        float cbp = 0.f;
        #pragma unroll
        for (int qi = 0; qi < 16; qi++) {
            int q4 = (qi + row) & 15;
            float4 mv = M4[q4];
            float4 iv = *(const float4*)(g_inv_sd + q4 * 4);
            float a = mv.x * iv.x, b = mv.y * iv.y, c = mv.z * iv.z, d = mv.w * iv.w;
            float4 qv = make_float4(a * a, b * b, c * c, d * d);
            if (h == 0) {
                float4 sv = S4[q4];
                float4 uv = make_float4(qv.x * sv.x, qv.y * sv.y, qv.z * sv.z, qv.w * sv.w);
                cbp += uv.x * sv.x + uv.y * sv.y + uv.z * sv.z + uv.w * sv.w;
                Ud[q4] = uv;
            } else {
                Ud[q4] = qv;
            }
        }
        if (h == 0) sCb[row] = -0.5f * cbp;
    }
    __syncthreads();

    // step 2: build frag-linear A levels (3 x 32KB)
    {
        const int gm = warp;                       // global mtile 0..7
        const int rA = gm * 16 + (lane >> 2), rB = rA + 8;
        const float2* U2 = (const float2*)Ubuf;
        #pragma unroll
        for (int ks = 0; ks < 8; ks++) {
            int k0 = ks * 16 + 2 * (lane & 3);
            float2 A0 = U2[rA * 64 + (k0 >> 1)];
            float2 A1 = U2[rB * 64 + (k0 >> 1)];
            float2 A2 = U2[rA * 64 + ((k0 + 8) >> 1)];
            float2 A3 = U2[rB * 64 + ((k0 + 8) >> 1)];
            uint32_t L0[4], L1[4], L2[4];
            split3(A0, L0[0], L1[0], L2[0]);
            split3(A1, L0[1], L1[1], L2[1]);
            split3(A2, L0[2], L1[2], L2[2]);
            split3(A3, L0[3], L1[3], L2[3]);
            uint32_t off = sb + (uint32_t)(((ks * 8 + gm) * 32 + lane) * 16);
            sts128(off,           L0[0], L0[1], L0[2], L0[3]);
            sts128(off + 32768u,  L1[0], L1[1], L1[2], L1[3]);
            sts128(off + 65536u,  L2[0], L2[1], L2[2], L2[3]);
        }
    }
    __syncthreads();

    float cbA[4], cbB[4];
    #pragma unroll
    for (int mi = 0; mi < 4; mi++) {
        cbA[mi] = sCb[wm * 64 + mi * 16 + (lane >> 2)];
        cbB[mi] = sCb[wm * 64 + mi * 16 + (lane >> 2) + 8];
    }
    float acc[4][8][4];
    #pragma unroll
    for (int mi = 0; mi < 4; mi++)
        #pragma unroll
        for (int j = 0; j < 8; j++)
            #pragma unroll
            for (int q = 0; q < 4; q++) acc[mi][j][q] = 0.f;
    float rmax[8];
    #pragma unroll
    for (int i = 0; i < 8; i++) rmax[i] = -1e30f;

    float* scratch = out + (size_t)NB * NN;
    int chunk = 0, pass = 0;
    #pragma unroll 1
    for (int u = 0; u < 24; u++) {
        if (u + 1 < 24) {
            const char* src = (const char*)g_Wb + (size_t)(u + 1) * 65536 + (size_t)t * 16;
            uint32_t dst = sb + SM_B + (uint32_t)((u + 1) & 1) * 65536u + (uint32_t)t * 16;
            #pragma unroll
            for (int i = 0; i < 16; i++) cp16(dst + i * 4096, src + (size_t)i * 4096);
            asm volatile("cp.async.commit_group;" ::: "memory");
            asm volatile("cp.async.wait_group 1;" ::: "memory");
        } else {
            asm volatile("cp.async.wait_group 0;" ::: "memory");
        }
        __syncthreads();

        const int aLvl = (pass == 2 || pass == 3) ? 1 : ((pass == 5) ? 2 : 0);
        const uint32_t aBase = sb + (uint32_t)aLvl * 32768u;
        const uint32_t bBase = sb + SM_B + (uint32_t)(u & 1) * 65536u
                             + (uint32_t)((wn * 8 * 32 + lane) * 8);
        #pragma unroll
        for (int ks = 0; ks < 8; ks++) {
            uint4 af[4];
            #pragma unroll
            for (int mi = 0; mi < 4; mi++)
                af[mi] = lds128(aBase + (uint32_t)(((ks * 8 + wm * 4 + mi) * 32 + lane) * 16));
            #pragma unroll
            for (int j = 0; j < 8; j++) {
                uint2 bf = lds64(bBase + (uint32_t)((ks * 32 + j) * 256));
                #pragma unroll
                for (int mi = 0; mi < 4; mi++) mma16816(acc[mi][j], af[mi], bf);
            }
        }
        __syncthreads();

        if (pass == 5) {
            const int colBase = chunk * 256 + wn * 64 + 2 * (lane & 3);
            #pragma unroll
            for (int j = 0; j < 8; j++) {
                const float2 lp = *(const float2*)(g_logprior + colBase + j * 8);
                #pragma unroll
                for (int mi = 0; mi < 4; mi++) {
                    const int rA = wm * 64 + mi * 16 + (lane >> 2);
                    float l00 = lp.x + fminf(acc[mi][j][0] + cbA[mi], 0.f);
                    float l01 = lp.y + fminf(acc[mi][j][1] + cbA[mi], 0.f);
                    float l10 = lp.x + fminf(acc[mi][j][2] + cbB[mi], 0.f);
                    float l11 = lp.y + fminf(acc[mi][j][3] + cbB[mi], 0.f);
                    rmax[mi * 2]     = fmaxf(rmax[mi * 2],     fmaxf(l00, l01));
                    rmax[mi * 2 + 1] = fmaxf(rmax[mi * 2 + 1], fmaxf(l10, l11));
                    *(float2*)(scratch + (size_t)(r0 + rA) * NN + colBase + j * 8)
                        = make_float2(l00, l01);
                    *(float2*)(scratch + (size_t)(r0 + rA + 8) * NN + colBase + j * 8)
                        = make_float2(l10, l11);
                    acc[mi][j][0] = 0.f; acc[mi][j][1] = 0.f;
                    acc[mi][j][2] = 0.f; acc[mi][j][3] = 0.f;
                }
            }
        }
        pass++; if (pass == 6) { pass = 0; chunk++; }
    }

    // cross-lane (cols within quad) then cross-warp (wn slices) row-max reduction
    #pragma unroll
    for (int i = 0; i < 8; i++) {
        rmax[i] = fmaxf(rmax[i], __shfl_xor_sync(0xffffffffu, rmax[i], 1));
        rmax[i] = fmaxf(rmax[i], __shfl_xor_sync(0xffffffffu, rmax[i], 2));
    }
    if ((lane & 3) == 0) {
        #pragma unroll
        for (int mi = 0; mi < 4; mi++) {
            int rA = wm * 64 + mi * 16 + (lane >> 2);
            sRm[wn * 128 + rA]     = rmax[mi * 2];
            sRm[wn * 128 + rA + 8] = rmax[mi * 2 + 1];
        }
    }
    __syncthreads();
    if (t < 128) {
        float m = fmaxf(fmaxf(sRm[t], sRm[128 + t]),
                        fmaxf(sRm[256 + t], sRm[384 + t]));
        g_rowmax[r0 + t] = m;
    }
}

// ---- kernel 2: warp-per-row truncated softmax ----
__global__ __launch_bounds__(256)
void softmax_k(float* __restrict__ out) {
    const int warp = threadIdx.x >> 5, lane = threadIdx.x & 31;
    const int row = blockIdx.x * 8 + warp;
    float* scratch = out + (size_t)NB * NN;
    const float4* L = (const float4*)(scratch + (size_t)row * NN);
    float4 x[8];
    #pragma unroll
    for (int i = 0; i < 8; i++) x[i] = L[lane + 32 * i];
    const float mx = g_rowmax[row];
    float s = 0.f;
    #pragma unroll
    for (int i = 0; i < 8; i++) {
        float p0 = __expf(x[i].x - mx); p0 = (p0 > 0.05f) ? p0 : 0.f;
        float p1 = __expf(x[i].y - mx); p1 = (p1 > 0.05f) ? p1 : 0.f;
        float p2 = __expf(x[i].z - mx); p2 = (p2 > 0.05f) ? p2 : 0.f;
        float p3 = __expf(x[i].w - mx); p3 = (p3 > 0.05f) ? p3 : 0.f;
        x[i] = make_float4(p0, p1, p2, p3);
        s += (p0 + p1) + (p2 + p3);
    }
    #pragma unroll
    for (int o = 16; o > 0; o >>= 1) s += __shfl_xor_sync(0xffffffffu, s, o);
    const float inv = 1.0f / s;
    float4* po = (float4*)(out + (size_t)row * NN);
    float4* lo = (float4*)(scratch + (size_t)row * NN);
    #pragma unroll
    for (int i = 0; i < 8; i++) {
        float4 v = x[i];
        float4 P = make_float4(v.x * inv, v.y * inv, v.z * inv, v.w * inv);
        float4 Lg = make_float4(__logf(P.x + 1e-20f), __logf(P.y + 1e-20f),
                                __logf(P.z + 1e-20f), __logf(P.w + 1e-20f));
        po[lane + 32 * i] = P;
        lo[lane + 32 * i] = Lg;
    }
}

extern "C" void kernel_launch(void* const* d_in, const int* in_sizes, int n_in,
                              void* d_out, int out_size) {
    const float* samples = (const float*)d_in[0];
    const float* mask    = (const float*)d_in[1];
    const float* cent    = (const float*)d_in[2];
    const float* sd      = (const float*)d_in[3];
    const float* lm      = (const float*)d_in[4];
    float* out = (float*)d_out;
    (void)in_sizes; (void)n_in; (void)out_size;

    cudaFuncSetAttribute(gemm_logits, cudaFuncAttributeMaxDynamicSharedMemorySize, SM_TOT);

    prep_all<<<768, 256>>>(cent, sd, lm);
    gemm_logits<<<NB / 128, 256, SM_TOT>>>(samples, mask, out);
    softmax_k<<<NB / 8, 256>>>(out);
}